// round 17
// baseline (speedup 1.0000x reference)
#include <cuda_runtime.h>
#include <cstdint>
#include <math.h>

#define N_NODES 25000
#define N_EDGES 400000
#define ROWS    50000
#define DIM     128
#define INV_DT  5.0f   // fp32(1/fp32(0.2)) == 5.0f; XLA fast-math does ts*5.0f

typedef unsigned long long ull;

#define NB_NODE  391   // (25000+63)/64
#define NB_TABLE 782   // (50000+63)/64
#define GRID_GEMM (3 * NB_NODE + 2 * NB_TABLE)   // 2737

// ---------------- device scratch (static; no allocation) ----------------
__device__ float g_Xq[(size_t)N_NODES * DIM];
__device__ float g_Xk[(size_t)N_NODES * DIM];
__device__ float g_Xv[(size_t)N_NODES * DIM];
__device__ float g_Tk[(size_t)ROWS * DIM];
__device__ float g_Tv[(size_t)ROWS * DIM];
// k-pair packed weights: [mat 0..4][kpair 0..63][col 0..127] ull
// mats: 0=WQ_top 1=WK_top 2=WV_top 3=WK_bot 4=WV_bot
__device__ ull g_Wp[5 * 64 * DIM];
__device__ float g_s[N_NODES];
__device__ float g_qt[DIM];
__device__ int   g_is64;

// ---------------- helpers ----------------
union U64F2 { ull u; float2 f; };

__device__ __forceinline__ ull fma2(ull a, ull b, ull c) {
    ull d;
    asm("fma.rn.f32x2 %0, %1, %2, %3;" : "=l"(d) : "l"(a), "l"(b), "l"(c));
    return d;
}

__device__ __forceinline__ int bucket(float tval) {
    int idx = (int)floorf(__fmul_rn(tval, INV_DT));
    return max(0, min(idx, ROWS - 1));
}

// ---------------- fused prep: wpack + detect + qt ----------------
__global__ void prep_kernel(const float* __restrict__ WQ,
                            const float* __restrict__ WK,
                            const float* __restrict__ WV,
                            const int* __restrict__ ei,
                            const float* __restrict__ TE,
                            const float* __restrict__ t) {
    int b = blockIdx.x;
    if (b < 160) {
        int idx = b * 256 + threadIdx.x;
        if (idx < 5 * 64 * DIM) {
            int m = idx >> 13;
            int rem = idx & 8191;
            int kp = rem >> 7;
            int c = rem & 127;
            const float* W = (m == 0) ? WQ : (m == 1 || m == 3) ? WK : WV;
            int row = ((m < 3) ? 0 : DIM) + 2 * kp;
            U64F2 u;
            u.f.x = W[(size_t)row * DIM + c];
            u.f.y = W[(size_t)(row + 1) * DIM + c];
            g_Wp[idx] = u.u;
        }
    } else if (b == 160) {
        if (threadIdx.x == 0) {
            int all0 = 1;
            for (int i = 0; i < 32; i++)
                if (ei[2 * i + 1] != 0) all0 = 0;
            g_is64 = all0;
        }
    } else {
        int o = threadIdx.x;
        if (o < DIM) {
            int idx = bucket(t[0]);
            const float* phi = TE + (size_t)idx * DIM;
            float acc = 0.0f;
            #pragma unroll 8
            for (int k = 0; k < DIM; k++)
                acc += phi[k] * WQ[(size_t)(DIM + k) * DIM + o];
            g_qt[o] = acc;
        }
    }
}

// dummy kernel: launch order prep(1), dummy(2), gemm(3), edge(4) -> ncu
// captures edge_kernel this round.
__global__ void dummy_kernel() {}

// ---------------- one-launch 5-matrix GEMM (r13 champion config) ---------
// block = 256 threads (8 warps); tile = 64 rows; W (64KB) + A (32KB) in SMEM.
// thread: cg = tid&31 -> cols {cg, cg+32, cg+64, cg+96}; warp w -> rows 8w..8w+7.
__global__ void __launch_bounds__(256, 2)
gemm_all(const float* __restrict__ x, const float* __restrict__ TE) {
    extern __shared__ ull Ws[];                     // [8192] ull = 64 KB
    float* As = (float*)(Ws + 8192);                // [64][128] = 32 KB

    int bid = blockIdx.x;
    const float* A;
    int M, tile;
    const ull* Wp;
    float* C;
    bool with_bias = false;
    if (bid < 3 * NB_NODE) {
        int mat = bid / NB_NODE;
        tile = bid - mat * NB_NODE;
        A = x; M = N_NODES;
        Wp = g_Wp + mat * 8192;
        C = (mat == 0) ? g_Xq : (mat == 1) ? g_Xk : g_Xv;
        with_bias = (mat == 0);
    } else {
        int rem = bid - 3 * NB_NODE;
        int mat = rem / NB_TABLE;
        tile = rem - mat * NB_TABLE;
        A = TE; M = ROWS;
        Wp = g_Wp + (3 + mat) * 8192;
        C = mat ? g_Tv : g_Tk;
    }

    int tid = threadIdx.x;
    int cg = tid & 31;
    int wid = tid >> 5;
    int rb = tile * 64;

    // stage W (64KB, coalesced 16B)
    {
        const ulonglong2* src = (const ulonglong2*)Wp;
        ulonglong2* dst = (ulonglong2*)Ws;
        #pragma unroll
        for (int i = 0; i < 16; i++)
            dst[tid + i * 256] = src[tid + i * 256];
    }
    // stage A tile (64 x 128 floats, float4-coalesced)
    #pragma unroll
    for (int i = 0; i < 8; i++) {
        int q = tid + i * 256;          // 0..2047
        int r = q >> 5, c4 = q & 31;
        int row = rb + r;
        float4 v = (row < M) ? ((const float4*)A)[(size_t)row * 32 + c4]
                             : make_float4(0.f, 0.f, 0.f, 0.f);
        *(float4*)&As[r * 128 + c4 * 4] = v;
    }
    __syncthreads();

    const float* Arow = As + wid * 8 * 128;

    ull acc[8][4];
    #pragma unroll
    for (int r = 0; r < 8; r++)
        #pragma unroll
        for (int j = 0; j < 4; j++) acc[r][j] = 0ull;

    #pragma unroll 2
    for (int kc = 0; kc < 32; kc++) {      // 4 k per chunk = 2 kpairs
        ulonglong2 a2[8];                  // (k0,k1),(k2,k3) per row (LDS.128 bcast)
        #pragma unroll
        for (int r = 0; r < 8; r++)
            a2[r] = *(const ulonglong2*)&Arow[r * 128 + kc * 4];
        #pragma unroll
        for (int kp = 0; kp < 2; kp++) {
            ull w[4];
            const ull* wrow = Ws + (kc * 2 + kp) * DIM + cg;
            #pragma unroll
            for (int j = 0; j < 4; j++) w[j] = wrow[j * 32];
            #pragma unroll
            for (int r = 0; r < 8; r++) {
                ull a = kp ? a2[r].y : a2[r].x;
                #pragma unroll
                for (int j = 0; j < 4; j++)
                    acc[r][j] = fma2(a, w[j], acc[r][j]);
            }
        }
    }

    float b[4] = {0.f, 0.f, 0.f, 0.f};
    if (with_bias) {
        #pragma unroll
        for (int j = 0; j < 4; j++) b[j] = g_qt[cg + 32 * j];
    }
    int r0 = rb + wid * 8;
    #pragma unroll
    for (int r = 0; r < 8; r++) {
        int row = r0 + r;
        if (row < M) {
            float* dst = C + (size_t)row * DIM + cg;
            #pragma unroll
            for (int j = 0; j < 4; j++) {
                U64F2 u; u.u = acc[r][j];
                dst[j * 32] = u.f.x + u.f.y + b[j];
            }
        }
    }
}

// ---------------- fused edge pass: TWO edges per warp --------------------
// Two independent gather->dot->scatter chains interleaved per warp doubles
// memory-level parallelism against the L2 gather latency.
__global__ void __launch_bounds__(256) edge_kernel(const void* __restrict__ ei_raw,
                                                   const float* __restrict__ ts,
                                                   float* __restrict__ out) {
    int gw = (blockIdx.x * 256 + threadIdx.x) >> 5;
    int lane = threadIdx.x & 31;
    int e0 = 2 * gw;
    int e1 = e0 + 1;
    if (e0 >= N_EDGES) return;
    bool has1 = (e1 < N_EDGES);
    int e1c = has1 ? e1 : e0;          // clamp: compute, discard at commit

    int src0, dst0, src1, dst1;
    if (g_is64) {
        const long long* p = (const long long*)ei_raw;
        src0 = (int)p[e0];             dst0 = (int)p[N_EDGES + e0];
        src1 = (int)p[e1c];            dst1 = (int)p[N_EDGES + e1c];
    } else {
        const int* p = (const int*)ei_raw;
        src0 = p[e0];                  dst0 = p[N_EDGES + e0];
        src1 = p[e1c];                 dst1 = p[N_EDGES + e1c];
    }
    int idx0 = bucket(__ldg(ts + e0));
    int idx1 = bucket(__ldg(ts + e1c));

    // interleaved gathers (6 independent loads in flight)
    float4 q0  = ((const float4*)g_Xq)[(size_t)dst0 * 32 + lane];
    float4 q1  = ((const float4*)g_Xq)[(size_t)dst1 * 32 + lane];
    float4 k0  = ((const float4*)g_Xk)[(size_t)src0 * 32 + lane];
    float4 k1  = ((const float4*)g_Xk)[(size_t)src1 * 32 + lane];
    float4 tk0 = ((const float4*)g_Tk)[(size_t)idx0 * 32 + lane];
    float4 tk1 = ((const float4*)g_Tk)[(size_t)idx1 * 32 + lane];

    float p0 = q0.x * (k0.x + tk0.x) + q0.y * (k0.y + tk0.y) +
               q0.z * (k0.z + tk0.z) + q0.w * (k0.w + tk0.w);
    float p1 = q1.x * (k1.x + tk1.x) + q1.y * (k1.y + tk1.y) +
               q1.z * (k1.z + tk1.z) + q1.w * (k1.w + tk1.w);
    #pragma unroll
    for (int off = 16; off; off >>= 1) {
        p0 += __shfl_xor_sync(0xffffffffu, p0, off);
        p1 += __shfl_xor_sync(0xffffffffu, p1, off);
    }

    float w0 = expf(p0);   // segment max skipped: |alpha| << 88, s >= 1
    float w1 = expf(p1);

    float4 v0  = ((const float4*)g_Xv)[(size_t)src0 * 32 + lane];
    float4 v1  = ((const float4*)g_Xv)[(size_t)src1 * 32 + lane];
    float4 tv0 = ((const float4*)g_Tv)[(size_t)idx0 * 32 + lane];
    float4 tv1 = ((const float4*)g_Tv)[(size_t)idx1 * 32 + lane];

    float4 r0 = make_float4(w0 * (v0.x + tv0.x), w0 * (v0.y + tv0.y),
                            w0 * (v0.z + tv0.z), w0 * (v0.w + tv0.w));
    atomicAdd(((float4*)(out + (size_t)dst0 * DIM)) + lane, r0);
    if (has1) {
        float4 r1 = make_float4(w1 * (v1.x + tv1.x), w1 * (v1.y + tv1.y),
                                w1 * (v1.z + tv1.z), w1 * (v1.w + tv1.w));
        atomicAdd(((float4*)(out + (size_t)dst1 * DIM)) + lane, r1);
    }
    if (lane == 0)
        atomicAdd(g_s + dst0, w0);
    if (lane == 1 && has1)
        atomicAdd(g_s + dst1, w1);
}

// ---------------- vectorized normalize ----------------
__global__ void __launch_bounds__(256) norm_kernel(float* __restrict__ out) {
    int i4 = blockIdx.x * 256 + threadIdx.x;     // float4 index
    if (i4 < N_NODES * 32) {
        int row = i4 >> 5;
        float rcp = __frcp_rn(g_s[row] + 1e-16f);
        float4 v = ((float4*)out)[i4];
        v.x *= rcp; v.y *= rcp; v.z *= rcp; v.w *= rcp;
        ((float4*)out)[i4] = v;
    }
}

// ---------------- launch ----------------
extern "C" void kernel_launch(void* const* d_in, const int* in_sizes, int n_in,
                              void* d_out, int out_size) {
    const float* x  = (const float*)d_in[0];
    const void*  ei = d_in[1];
    const float* ts = (const float*)d_in[2];
    const float* t  = (const float*)d_in[3];
    const float* TE = (const float*)d_in[4];
    const float* WQ = (const float*)d_in[5];
    const float* WK = (const float*)d_in[6];
    const float* WV = (const float*)d_in[7];
    float* out = (float*)d_out;

    float* s;
    cudaGetSymbolAddress((void**)&s, g_s);

    const int SMEM = 96 * 1024 + 1024;
    cudaFuncSetAttribute(gemm_all, cudaFuncAttributeMaxDynamicSharedMemorySize, SMEM);

    prep_kernel<<<162, 256>>>(WQ, WK, WV, (const int*)ei, TE, t);
    cudaMemsetAsync(s, 0, N_NODES * sizeof(float));
    cudaMemsetAsync(d_out, 0, (size_t)N_NODES * DIM * sizeof(float));

    // one dummy: prep(1), dummy(2), gemm(3), edge(4) -> ncu captures edge
    dummy_kernel<<<1, 32>>>();

    gemm_all<<<GRID_GEMM, 256, SMEM>>>(x, TE);

    // two edges per warp: 200k warps
    edge_kernel<<<(N_EDGES / 2 * 32 + 255) / 256, 256>>>(ei, ts, out);
    norm_kernel<<<(N_NODES * 32 + 255) / 256, 256>>>(out);
}